// round 10
// baseline (speedup 1.0000x reference)
#include <cuda_runtime.h>

#define NB 16
#define CH 64
#define SS 256
#define M0 16
#define NMODE 32
#define PLANE (SS*SS)

typedef unsigned long long u64;

__device__ __forceinline__ u64 fma2(u64 a, u64 b, u64 c) {
    u64 d; asm("fma.rn.f32x2 %0,%1,%2,%3;" : "=l"(d) : "l"(a), "l"(b), "l"(c)); return d;
}
__device__ __forceinline__ float2 unpk(u64 v) {
    unsigned lo, hi; asm("mov.b64 {%0,%1},%2;" : "=r"(lo), "=r"(hi) : "l"(v));
    return make_float2(__uint_as_float(lo), __uint_as_float(hi));
}
__device__ __forceinline__ u64 pk(float a, float b) {
    u64 d; asm("mov.b64 %0,{%1,%2};" : "=l"(d) : "r"(__float_as_uint(a)), "r"(__float_as_uint(b)));
    return d;
}
__device__ __forceinline__ void ldsv2(u64& a, u64& b, const void* p) {
    unsigned ad = (unsigned)__cvta_generic_to_shared(p);
    asm("ld.shared.v2.u64 {%0,%1},[%2];" : "=l"(a), "=l"(b) : "r"(ad));
}

// ---------------- device scratch ----------------
__device__ float  g_h2[2][NB*32*SS*SS*2];      // [b][c/2][x][y][2]
__device__ float  g_Ar[NB*CH*M0*SS];           // [b][c][ky][x]
__device__ float  g_Ai[NB*CH*M0*SS];
__device__ float2 g_ft[NMODE*M0*NB*CH];        // [mode][b][i]
__device__ float2 g_oft[NMODE*M0*NB*CH];
__device__ float2 g_t [NB*CH*SS*M0];           // [b][o][x][ky]
__device__ float2 g_W [4*NMODE*M0*CH*CH];      // [blk][mode][i][o]
__device__ float  g_tyc[M0*SS];                // cos(2pi ky y/256)
__device__ float  g_tys[M0*SS];                // -sin
__device__ float  g_xc[NMODE*SS];              // cos(2pi kxp x/256)
__device__ float  g_xs[NMODE*SS];              // sin
__device__ float4 g_ty4[M0*SS];                // (c,c,-s,-s)

// ---------------- trig tables ----------------
__global__ void k_trig() {
    int t = blockIdx.x * blockDim.x + threadIdx.x;
    if (t < M0 * SS) {
        int ky = t >> 8, y = t & 255;
        float s, c;
        sincospif((float)(ky * y) / 128.0f, &s, &c);   // exact integer arg
        g_tyc[t] = c; g_tys[t] = -s;
        g_ty4[t] = make_float4(c, c, -s, -s);
    } else if (t < M0 * SS + NMODE * SS) {
        int k = t - M0 * SS;
        int m = k >> 8, x = k & 255;
        int kxp = (m < 16) ? m : (m - 32);
        float s, c;
        sincospif((float)(kxp * x) / 128.0f, &s, &c);
        g_xc[k] = c; g_xs[k] = s;
    }
}

// ---------------- weight re-layout ----------------
__global__ void k_wprep(const float2* __restrict__ w1, const float2* __restrict__ w2) {
    int idx = blockIdx.x * blockDim.x + threadIdx.x;
    int o = idx & 63, i = (idx >> 6) & 63, ky = (idx >> 12) & 15;
    int m = (idx >> 16) & 31, blk = (idx >> 21);
    const float2* src = (m < 16) ? w1 : w2;
    int mx = (m < 16) ? m : (m - 16);
    g_W[idx] = src[((((long)blk * 64 + i) * 64 + o) * 16 + mx) * 16 + ky];
}

// ---------------- lift ----------------
__global__ void k_lift(const float* __restrict__ x, const float* __restrict__ w0,
                       const float* __restrict__ b0) {
    __shared__ float sw[192], sb[64];
    int t = threadIdx.x;
    if (t < 192) sw[t] = w0[t];
    if (t < 64)  sb[t] = b0[t];
    __syncthreads();
    int b = blockIdx.y, xx = blockIdx.x, y = t;
    const float* xp = x + (((long)b * SS + xx) * SS + y) * 3;
    float x0 = xp[0], x1 = xp[1], x2 = xp[2];
    float2* out = (float2*)g_h2[0];
#pragma unroll
    for (int cp = 0; cp < 32; cp++) {
        int c0 = 2 * cp;
        float v0 = x0 * sw[c0]   + x1 * sw[64 + c0]   + x2 * sw[128 + c0]   + sb[c0];
        float v1 = x0 * sw[c0+1] + x1 * sw[64 + c0+1] + x2 * sw[128 + c0+1] + sb[c0+1];
        out[((long)(b * 32 + cp) * SS + xx) * SS + y] = make_float2(v0, v1);
    }
}

// ---------------- forward y-DFT ----------------
// CTA per (cp, xq, b): 128 thr = 4 warps; warp = ky-half(8 ky) x x-group.
// thread: 2 x, 8 ky; acc 32 u64. crossbar 12cyc vs FFMA2 16cyc per y.
#define SMEM_DFTY (32*130*8 + 16*32*16)
__global__ void __launch_bounds__(128) k_dfty(int sel) {
    extern __shared__ float sm[];
    u64* sh = (u64*)sm;                          // [32 y][130 x-slots]
    float4* t4 = (float4*)(sm + 32 * 130 * 2);   // [16 ky][32 y]
    int b = blockIdx.z, xq = blockIdx.y, cp = blockIdx.x, t = threadIdx.x;
    const u64* gp = (const u64*)(g_h2[sel]) + (long)(b * 32 + cp) * PLANE
                  + (long)xq * 128 * SS;
    int w = t >> 5, lane = t & 31;
    int kyh = (w & 1) * 8, xg = w >> 1;
    int xl1 = xg * 64 + lane, xl2 = xl1 + 32;
    u64 aR[2][8], aI[2][8];
#pragma unroll
    for (int j = 0; j < 2; j++)
#pragma unroll
        for (int k = 0; k < 8; k++) { aR[j][k] = 0; aI[j][k] = 0; }

    for (int yc = 0; yc < 8; yc++) {
#pragma unroll
        for (int i = 0; i < 32; i++) {
            int idx = i * 128 + t, xx = idx >> 5, yy = idx & 31;
            sh[yy * 130 + xx] = gp[xx * 256 + yc * 32 + yy];
        }
#pragma unroll
        for (int i = 0; i < 4; i++) {
            int idx = i * 128 + t, ky = idx >> 5, yy = idx & 31;
            t4[idx] = g_ty4[ky * 256 + yc * 32 + yy];
        }
        __syncthreads();
#pragma unroll 4
        for (int y = 0; y < 32; y++) {
            u64 h1 = sh[y * 130 + xl1], h2v = sh[y * 130 + xl2];
#pragma unroll
            for (int k = 0; k < 8; k++) {
                u64 cc, ss;
                ldsv2(cc, ss, &t4[(kyh + k) * 32 + y]);
                aR[0][k] = fma2(h1, cc, aR[0][k]);  aI[0][k] = fma2(h1, ss, aI[0][k]);
                aR[1][k] = fma2(h2v, cc, aR[1][k]); aI[1][k] = fma2(h2v, ss, aI[1][k]);
            }
        }
        __syncthreads();
    }
    const float sc = 1.0f / 65536.0f;
#pragma unroll
    for (int j = 0; j < 2; j++) {
        int x = xq * 128 + (j ? xl2 : xl1);
#pragma unroll
        for (int k = 0; k < 8; k++) {
            int ky = kyh + k;
            long p0 = ((long)((b * 64 + 2 * cp) * 16 + ky)) * 256 + x;
            long p1 = ((long)((b * 64 + 2 * cp + 1) * 16 + ky)) * 256 + x;
            float2 r = unpk(aR[j][k]), ii = unpk(aI[j][k]);
            g_Ar[p0] = r.x * sc;  g_Ar[p1] = r.y * sc;
            g_Ai[p0] = ii.x * sc; g_Ai[p1] = ii.y * sc;
        }
    }
}

// ---------------- forward x-DFT ----------------
__global__ void __launch_bounds__(512) k_dftx() {
    __shared__ float sAr[16 * 258];
    __shared__ float sAi[16 * 258];
    int b = blockIdx.y, i = blockIdx.x;
    long abase = (long)((b * CH + i) * M0) * SS;
    for (int k = threadIdx.x; k < 4096; k += 512) {
        int ky = k >> 8, x = k & 255;
        sAr[ky * 258 + x] = g_Ar[abase + k];
        sAi[ky * 258 + x] = g_Ai[abase + k];
    }
    __syncthreads();
    int ky = threadIdx.x & 15, m = threadIdx.x >> 4;
    const u64* arp = (const u64*)(sAr + ky * 258);
    const u64* aip = (const u64*)(sAi + ky * 258);
    const u64* cp = (const u64*)(g_xc + m * 256);
    const u64* sp = (const u64*)(g_xs + m * 256);
    u64 RC = 0, IS = 0, IC = 0, RS = 0;
#pragma unroll 8
    for (int xp = 0; xp < 128; xp++) {
        u64 c2 = cp[xp], s2 = sp[xp];
        u64 ar = arp[xp], ai = aip[xp];
        RC = fma2(ar, c2, RC); IS = fma2(ai, s2, IS);
        IC = fma2(ai, c2, IC); RS = fma2(ar, s2, RS);
    }
    float2 rc = unpk(RC), is = unpk(IS), ic = unpk(IC), rs = unpk(RS);
    g_ft[(long)(m * M0 + ky) * (NB * CH) + b * CH + i] =
        make_float2(rc.x + rc.y + is.x + is.y, ic.x + ic.y - rs.x - rs.y);
}

// ---------------- per-mode channel mix ----------------
__global__ void k_mix(int blk) {
    __shared__ float2 F[NB * CH];
    int mode = blockIdx.x;
    const float2* src = g_ft + (long)mode * (NB * CH);
    for (int k = threadIdx.x; k < NB * CH; k += 256) F[k] = src[k];
    __syncthreads();
    const float2* W = g_W + ((long)blk * (NMODE * M0) + mode) * (CH * CH);
    int o = threadIdx.x & 63, bg = threadIdx.x >> 6;
    float accr[4] = {0,0,0,0}, acci[4] = {0,0,0,0};
    for (int i = 0; i < CH; i++) {
        float2 w = W[i * CH + o];
#pragma unroll
        for (int bb = 0; bb < 4; bb++) {
            float2 f = F[(bg * 4 + bb) * CH + i];
            accr[bb] += f.x * w.x - f.y * w.y;
            acci[bb] += f.x * w.y + f.y * w.x;
        }
    }
#pragma unroll
    for (int bb = 0; bb < 4; bb++)
        g_oft[(long)mode * (NB * CH) + (bg * 4 + bb) * CH + o] = make_float2(accr[bb], acci[bb]);
}

// ---------------- inverse x-DFT ----------------
__global__ void k_idftx() {
    __shared__ float2 so[NMODE * M0];
    int b = blockIdx.y, o = blockIdx.x;
    for (int k = threadIdx.x; k < NMODE * M0; k += 256)
        so[k] = g_oft[(long)k * (NB * CH) + b * CH + o];
    __syncthreads();
    int x = threadIdx.x;
    float accr[M0], acci[M0];
#pragma unroll
    for (int ky = 0; ky < M0; ky++) { accr[ky] = 0.f; acci[ky] = 0.f; }
    for (int m = 0; m < NMODE; m++) {
        float c = g_xc[m * 256 + x], s = g_xs[m * 256 + x];
#pragma unroll
        for (int ky = 0; ky < M0; ky++) {
            float2 a = so[m * M0 + ky];
            accr[ky] += a.x * c - a.y * s;
            acci[ky] += a.x * s + a.y * c;
        }
    }
    float2* dst = g_t + ((long)(b * CH + o) * SS + x) * M0;
#pragma unroll
    for (int ky = 0; ky < M0; ky++) dst[ky] = make_float2(accr[ky], acci[ky]);
}

// ---------------- block epilogue: K=96 GEMM, 128 thr, warp=16 o, y-tile 64 ----
#define SMEM_FINAL (48*64*8 + 48*66*8 + 64*4)
__global__ void __launch_bounds__(128) k_final(int sel, const float* __restrict__ cw,
                                               const float* __restrict__ cb, int relu) {
    extern __shared__ float sm[];
    u64* wA = (u64*)sm;                    // [48 kp][64 o]
    u64* Bm = wA + 48 * 64;                // [48 kp][66] (64 y used)
    float* cbs = (float*)(Bm + 48 * 66);
    int t = threadIdx.x;
    int b = blockIdx.z, xx = blockIdx.y, yb = blockIdx.x * 64;

    const u64* cwp = (const u64*)cw;
    for (int idx = t; idx < 2048; idx += 128) {
        int o = idx >> 5, ip = idx & 31;
        wA[ip * 64 + o] = cwp[o * 32 + ip];
    }
    for (int idx = t; idx < 512; idx += 128) {
        int o = idx >> 3, kp = idx & 7;
        const float2* tp = g_t + ((long)(b * 64 + o) * 256 + xx) * 16;
        float2 v0 = tp[2 * kp], v1 = tp[2 * kp + 1];
        float f0 = (kp == 0) ? 1.f : 2.f;
        wA[(32 + kp) * 64 + o] = pk(f0 * v0.x, 2.f * v1.x);
        wA[(40 + kp) * 64 + o] = pk(f0 * v0.y, 2.f * v1.y);
    }
    const u64* hp = (const u64*)(g_h2[sel]);
    for (int idx = t; idx < 2048; idx += 128) {
        int ip = idx >> 6, yl = idx & 63;
        Bm[ip * 66 + yl] = hp[((long)(b * 32 + ip) * 256 + xx) * 256 + yb + yl];
    }
    for (int idx = t; idx < 1024; idx += 128) {
        int r = idx >> 6, yl = idx & 63;
        int kp = r & 7, y = yb + yl, ky0 = 2 * kp;
        if (r < 8)
            Bm[(32 + kp) * 66 + yl] = pk(g_tyc[ky0 * 256 + y], g_tyc[(ky0 + 1) * 256 + y]);
        else
            Bm[(40 + kp) * 66 + yl] = pk(g_tys[ky0 * 256 + y], g_tys[(ky0 + 1) * 256 + y]);
    }
    if (t < 64) cbs[t] = cb[t];
    __syncthreads();

    int w = t >> 5, lane = t & 31;
    int ob = w * 16;
    u64 acc[16][2];
#pragma unroll
    for (int oo = 0; oo < 16; oo++) { acc[oo][0] = 0; acc[oo][1] = 0; }

    for (int k = 0; k < 48; k++) {
        u64 b0 = Bm[k * 66 + lane];
        u64 b1 = Bm[k * 66 + 32 + lane];
#pragma unroll
        for (int op = 0; op < 8; op++) {
            u64 a0, a1;
            ldsv2(a0, a1, &wA[k * 64 + ob + 2 * op]);
            acc[2*op  ][0] = fma2(a0, b0, acc[2*op  ][0]);
            acc[2*op  ][1] = fma2(a0, b1, acc[2*op  ][1]);
            acc[2*op+1][0] = fma2(a1, b0, acc[2*op+1][0]);
            acc[2*op+1][1] = fma2(a1, b1, acc[2*op+1][1]);
        }
    }
    __syncthreads();                 // done reading Bm; reuse as output stage
    u64* S = Bm;                     // [32 op][66]
#pragma unroll
    for (int op = 0; op < 8; op++) {
        int o0 = ob + 2 * op;
        float b0f = cbs[o0], b1f = cbs[o0 + 1];
#pragma unroll
        for (int s = 0; s < 2; s++) {
            int y = s * 32 + lane;
            float2 v0 = unpk(acc[2*op][s]), v1 = unpk(acc[2*op+1][s]);
            float r0 = v0.x + v0.y + b0f, r1 = v1.x + v1.y + b1f;
            if (relu) { r0 = fmaxf(r0, 0.f); r1 = fmaxf(r1, 0.f); }
            S[(o0 >> 1) * 66 + y] = pk(r0, r1);
        }
    }
    __syncthreads();
    u64* ho = (u64*)(g_h2[sel ^ 1]);
    for (int idx = t; idx < 2048; idx += 128) {
        int op = idx >> 6, yl = idx & 63;
        ho[((long)(b * 32 + op) * 256 + xx) * 256 + yb + yl] = S[op * 66 + yl];
    }
}

// ---------------- fused fc1+relu+fc2: 128 thr, warp=16 j, 4 passes of 64 j ----
#define SMEM_FC (32*64*8 + 32*66*8 + 3*64*4)
__global__ void __launch_bounds__(128) k_fc(int sel, const float* __restrict__ fc1w,
                                            const float* __restrict__ fc1b,
                                            const float* __restrict__ fc2w,
                                            const float* __restrict__ fc2b,
                                            float* __restrict__ out) {
    extern __shared__ float sm[];
    u64* wA = (u64*)sm;                    // [32 ip][64 j]
    u64* Bm = wA + 32 * 64;                // [32 ip][66] (64 y used)
    float* b1s = (float*)(Bm + 32 * 66);   // [64]
    float* f2s = b1s + 64;
    float* sred = f2s + 64;
    int t = threadIdx.x;
    int b = blockIdx.z, xx = blockIdx.y, yb = blockIdx.x * 64;
    int w = t >> 5, lane = t & 31, jblk = w * 16;

    const u64* hp = (const u64*)(g_h2[sel]);
    for (int idx = t; idx < 2048; idx += 128) {
        int ip = idx >> 6, yl = idx & 63;
        Bm[ip * 66 + yl] = hp[((long)(b * 32 + ip) * 256 + xx) * 256 + yb + yl];
    }
    if (t < 64) sred[t] = fc2b[0];
    __syncthreads();

    float p0 = 0.f, p1 = 0.f;
    for (int pass = 0; pass < 4; pass++) {
        int jb0 = pass * 64;
        for (int idx = t; idx < 2048; idx += 128) {
            int ip = idx >> 6, j = idx & 63;
            wA[ip * 64 + j] = pk(fc1w[(2 * ip) * 256 + jb0 + j],
                                 fc1w[(2 * ip + 1) * 256 + jb0 + j]);
        }
        if (t < 64) { b1s[t] = fc1b[jb0 + t]; f2s[t] = fc2w[jb0 + t]; }
        __syncthreads();

        u64 acc[16][2];
#pragma unroll
        for (int jj = 0; jj < 16; jj++) { acc[jj][0] = 0; acc[jj][1] = 0; }
        for (int ip = 0; ip < 32; ip++) {
            u64 b0 = Bm[ip * 66 + lane];
            u64 b1 = Bm[ip * 66 + 32 + lane];
#pragma unroll
            for (int op = 0; op < 8; op++) {
                u64 a0, a1;
                ldsv2(a0, a1, &wA[ip * 64 + jblk + 2 * op]);
                acc[2*op  ][0] = fma2(a0, b0, acc[2*op  ][0]);
                acc[2*op  ][1] = fma2(a0, b1, acc[2*op  ][1]);
                acc[2*op+1][0] = fma2(a1, b0, acc[2*op+1][0]);
                acc[2*op+1][1] = fma2(a1, b1, acc[2*op+1][1]);
            }
        }
#pragma unroll
        for (int jj = 0; jj < 16; jj++) {
            float bias = b1s[jblk + jj], f2 = f2s[jblk + jj];
            float2 v0 = unpk(acc[jj][0]), v1 = unpk(acc[jj][1]);
            p0 += fmaxf(v0.x + v0.y + bias, 0.f) * f2;
            p1 += fmaxf(v1.x + v1.y + bias, 0.f) * f2;
        }
        __syncthreads();   // before wA overwrite next pass
    }
    atomicAdd(&sred[lane], p0);
    atomicAdd(&sred[32 + lane], p1);
    __syncthreads();
    if (t < 64) out[((long)b * 256 + xx) * 256 + yb + t] = sred[t];
}

// ---------------- launch ----------------
extern "C" void kernel_launch(void* const* d_in, const int* in_sizes, int n_in,
                              void* d_out, int out_size) {
    const float* x    = (const float*)d_in[0];
    const float* fc0w = (const float*)d_in[1];
    const float* fc0b = (const float*)d_in[2];
    const float2* w1  = (const float2*)d_in[3];
    const float2* w2  = (const float2*)d_in[4];
    const float* cw   = (const float*)d_in[5];
    const float* cb   = (const float*)d_in[6];
    const float* fc1w = (const float*)d_in[7];
    const float* fc1b = (const float*)d_in[8];
    const float* fc2w = (const float*)d_in[9];
    const float* fc2b = (const float*)d_in[10];
    float* out = (float*)d_out;

    cudaFuncSetAttribute(k_dfty,  cudaFuncAttributeMaxDynamicSharedMemorySize, SMEM_DFTY);
    cudaFuncSetAttribute(k_final, cudaFuncAttributeMaxDynamicSharedMemorySize, SMEM_FINAL);
    cudaFuncSetAttribute(k_fc,    cudaFuncAttributeMaxDynamicSharedMemorySize, SMEM_FC);

    k_trig<<<48, 256>>>();
    k_wprep<<<(4 * NMODE * M0 * CH * CH) / 256, 256>>>(w1, w2);
    k_lift<<<dim3(SS, NB), 256>>>(x, fc0w, fc0b);

    int cur = 0;
    for (int blk = 0; blk < 4; blk++) {
        k_dfty<<<dim3(32, 2, NB), 128, SMEM_DFTY>>>(cur);
        k_dftx<<<dim3(CH, NB), 512>>>();
        k_mix<<<NMODE * M0, 256>>>(blk);
        k_idftx<<<dim3(CH, NB), 256>>>();
        k_final<<<dim3(4, SS, NB), 128, SMEM_FINAL>>>(cur, cw + (long)blk * CH * CH,
                                                      cb + blk * CH, blk < 3 ? 1 : 0);
        cur ^= 1;
    }
    k_fc<<<dim3(4, SS, NB), 128, SMEM_FC>>>(cur, fc1w, fc1b, fc2w, fc2b, out);
}

// round 14
// speedup vs baseline: 1.8795x; 1.8795x over previous
#include <cuda_runtime.h>
#include <cuda_bf16.h>

#define NB 16
#define CH 64
#define SS 256
#define M0 16
#define NMODE 32
#define PLANE (SS*SS)

typedef unsigned long long u64;

__device__ __forceinline__ u64 fma2(u64 a, u64 b, u64 c) {
    u64 d; asm("fma.rn.f32x2 %0,%1,%2,%3;" : "=l"(d) : "l"(a), "l"(b), "l"(c)); return d;
}
__device__ __forceinline__ float2 unpk(u64 v) {
    unsigned lo, hi; asm("mov.b64 {%0,%1},%2;" : "=r"(lo), "=r"(hi) : "l"(v));
    return make_float2(__uint_as_float(lo), __uint_as_float(hi));
}
__device__ __forceinline__ u64 pk(float a, float b) {
    u64 d; asm("mov.b64 %0,{%1,%2};" : "=l"(d) : "r"(__float_as_uint(a)), "r"(__float_as_uint(b)));
    return d;
}
__device__ __forceinline__ void ldsv2(u64& a, u64& b, const void* p) {
    unsigned ad = (unsigned)__cvta_generic_to_shared(p);
    asm("ld.shared.v2.u64 {%0,%1},[%2];" : "=l"(a), "=l"(b) : "r"(ad));
}
__device__ __forceinline__ unsigned bfpair(float lo, float hi) {
    __nv_bfloat162 q;
    q.x = __float2bfloat16(lo); q.y = __float2bfloat16(hi);
    return *reinterpret_cast<unsigned*>(&q);
}
__device__ __forceinline__ void mma_bf16(float* c, const unsigned* a, unsigned b0, unsigned b1) {
    asm("mma.sync.aligned.m16n8k16.row.col.f32.bf16.bf16.f32 "
        "{%0,%1,%2,%3}, {%4,%5,%6,%7}, {%8,%9}, {%0,%1,%2,%3};"
        : "+f"(c[0]), "+f"(c[1]), "+f"(c[2]), "+f"(c[3])
        : "r"(a[0]), "r"(a[1]), "r"(a[2]), "r"(a[3]), "r"(b0), "r"(b1));
}

// ---------------- device scratch ----------------
__device__ float  g_h2[2][NB*32*SS*SS*2];      // [b][c/2][x][y][2]
__device__ float  g_Ar[NB*CH*M0*SS];           // [b][c][ky][x]
__device__ float  g_Ai[NB*CH*M0*SS];
__device__ float2 g_ft[NMODE*M0*NB*CH];        // [mode][b][i]
__device__ float2 g_oft[NMODE*M0*NB*CH];
__device__ float2 g_t [NB*CH*SS*M0];           // [b][o][x][ky]
__device__ float2 g_W [4*NMODE*M0*CH*CH];      // [blk][mode][i][o]
__device__ float  g_tyc[M0*SS];                // cos(2pi ky y/256)
__device__ float  g_tys[M0*SS];                // -sin
__device__ float  g_xc[NMODE*SS];              // cos(2pi kxp x/256)
__device__ float  g_xs[NMODE*SS];              // sin
__device__ float4 g_ty4[M0*SS];                // (c,c,-s,-s)
__device__ unsigned g_Wh[256*32];              // fc1w bf16-hi pairs [j][kp]
__device__ unsigned g_Wl[256*32];              // fc1w bf16-lo pairs

// ---------------- trig tables ----------------
__global__ void k_trig() {
    int t = blockIdx.x * blockDim.x + threadIdx.x;
    if (t < M0 * SS) {
        int ky = t >> 8, y = t & 255;
        float s, c;
        sincospif((float)(ky * y) / 128.0f, &s, &c);   // exact integer arg
        g_tyc[t] = c; g_tys[t] = -s;
        g_ty4[t] = make_float4(c, c, -s, -s);
    } else if (t < M0 * SS + NMODE * SS) {
        int k = t - M0 * SS;
        int m = k >> 8, x = k & 255;
        int kxp = (m < 16) ? m : (m - 32);
        float s, c;
        sincospif((float)(kxp * x) / 128.0f, &s, &c);
        g_xc[k] = c; g_xs[k] = s;
    }
}

// ---------------- weight re-layouts ----------------
__global__ void k_wprep(const float2* __restrict__ w1, const float2* __restrict__ w2) {
    int idx = blockIdx.x * blockDim.x + threadIdx.x;
    int o = idx & 63, i = (idx >> 6) & 63, ky = (idx >> 12) & 15;
    int m = (idx >> 16) & 31, blk = (idx >> 21);
    const float2* src = (m < 16) ? w1 : w2;
    int mx = (m < 16) ? m : (m - 16);
    g_W[idx] = src[((((long)blk * 64 + i) * 64 + o) * 16 + mx) * 16 + ky];
}

__global__ void k_fcprep(const float* __restrict__ fc1w) {
    int idx = blockIdx.x * 256 + threadIdx.x;   // 8192: j*32+kp
    int j = idx >> 5, kp = idx & 31;
    float w0 = fc1w[(2 * kp) * 256 + j], w1 = fc1w[(2 * kp + 1) * 256 + j];
    __nv_bfloat16 h0 = __float2bfloat16(w0), h1 = __float2bfloat16(w1);
    float r0 = w0 - __bfloat162float(h0), r1 = w1 - __bfloat162float(h1);
    __nv_bfloat162 q; q.x = h0; q.y = h1;
    g_Wh[idx] = *reinterpret_cast<unsigned*>(&q);
    g_Wl[idx] = bfpair(r0, r1);
}

// ---------------- lift ----------------
__global__ void k_lift(const float* __restrict__ x, const float* __restrict__ w0,
                       const float* __restrict__ b0) {
    __shared__ float sw[192], sb[64];
    int t = threadIdx.x;
    if (t < 192) sw[t] = w0[t];
    if (t < 64)  sb[t] = b0[t];
    __syncthreads();
    int b = blockIdx.y, xx = blockIdx.x, y = t;
    const float* xp = x + (((long)b * SS + xx) * SS + y) * 3;
    float x0 = xp[0], x1 = xp[1], x2 = xp[2];
    float2* out = (float2*)g_h2[0];
#pragma unroll
    for (int cp = 0; cp < 32; cp++) {
        int c0 = 2 * cp;
        float v0 = x0 * sw[c0]   + x1 * sw[64 + c0]   + x2 * sw[128 + c0]   + sb[c0];
        float v1 = x0 * sw[c0+1] + x1 * sw[64 + c0+1] + x2 * sw[128 + c0+1] + sb[c0+1];
        out[((long)(b * 32 + cp) * SS + xx) * SS + y] = make_float2(v0, v1);
    }
}

// ---------------- forward y-DFT (R9 known-good) ----------------
#define SMEM_DFTY (32*65*8 + 16*32*16)
__global__ void __launch_bounds__(128) k_dfty(int sel) {
    extern __shared__ float sm[];
    u64* sh = (u64*)sm;                          // [32 y][65 x]
    float4* t4 = (float4*)(sm + 32 * 65 * 2);    // [16 ky][32 y]
    int b = blockIdx.z, xq = blockIdx.y, cp = blockIdx.x, t = threadIdx.x;
    const u64* gp = (const u64*)(g_h2[sel]) + (long)(b * 32 + cp) * PLANE
                  + (long)(xq * 64) * SS;
    int w = t >> 5, lane = t & 31, ky0 = w * 4;
    u64 aR[2][4], aI[2][4];
#pragma unroll
    for (int j = 0; j < 2; j++)
#pragma unroll
        for (int k = 0; k < 4; k++) { aR[j][k] = 0; aI[j][k] = 0; }

    for (int yc = 0; yc < 8; yc++) {
#pragma unroll
        for (int i = 0; i < 16; i++) {
            int idx = i * 128 + t, xx = idx >> 5, yy = idx & 31;
            sh[yy * 65 + xx] = gp[xx * 256 + yc * 32 + yy];
        }
#pragma unroll
        for (int i = 0; i < 4; i++) {
            int idx = i * 128 + t, ky = idx >> 5, yy = idx & 31;
            t4[idx] = g_ty4[ky * 256 + yc * 32 + yy];
        }
        __syncthreads();
#pragma unroll 8
        for (int y = 0; y < 32; y++) {
            u64 h1 = sh[y * 65 + lane], h2v = sh[y * 65 + 32 + lane];
#pragma unroll
            for (int k = 0; k < 4; k++) {
                u64 cc, ss;
                ldsv2(cc, ss, &t4[(ky0 + k) * 32 + y]);
                aR[0][k] = fma2(h1, cc, aR[0][k]);  aI[0][k] = fma2(h1, ss, aI[0][k]);
                aR[1][k] = fma2(h2v, cc, aR[1][k]); aI[1][k] = fma2(h2v, ss, aI[1][k]);
            }
        }
        __syncthreads();
    }
    const float sc = 1.0f / 65536.0f;
#pragma unroll
    for (int j = 0; j < 2; j++) {
        int x = xq * 64 + lane + j * 32;
#pragma unroll
        for (int k = 0; k < 4; k++) {
            int ky = ky0 + k;
            long p0 = ((long)((b * 64 + 2 * cp) * 16 + ky)) * 256 + x;
            long p1 = ((long)((b * 64 + 2 * cp + 1) * 16 + ky)) * 256 + x;
            float2 r = unpk(aR[j][k]), ii = unpk(aI[j][k]);
            g_Ar[p0] = r.x * sc;  g_Ar[p1] = r.y * sc;
            g_Ai[p0] = ii.x * sc; g_Ai[p1] = ii.y * sc;
        }
    }
}

// ---------------- forward x-DFT ----------------
__global__ void __launch_bounds__(512) k_dftx() {
    __shared__ float sAr[16 * 258];
    __shared__ float sAi[16 * 258];
    int b = blockIdx.y, i = blockIdx.x;
    long abase = (long)((b * CH + i) * M0) * SS;
    for (int k = threadIdx.x; k < 4096; k += 512) {
        int ky = k >> 8, x = k & 255;
        sAr[ky * 258 + x] = g_Ar[abase + k];
        sAi[ky * 258 + x] = g_Ai[abase + k];
    }
    __syncthreads();
    int ky = threadIdx.x & 15, m = threadIdx.x >> 4;
    const u64* arp = (const u64*)(sAr + ky * 258);
    const u64* aip = (const u64*)(sAi + ky * 258);
    const u64* cp = (const u64*)(g_xc + m * 256);
    const u64* sp = (const u64*)(g_xs + m * 256);
    u64 RC = 0, IS = 0, IC = 0, RS = 0;
#pragma unroll 8
    for (int xp = 0; xp < 128; xp++) {
        u64 c2 = cp[xp], s2 = sp[xp];
        u64 ar = arp[xp], ai = aip[xp];
        RC = fma2(ar, c2, RC); IS = fma2(ai, s2, IS);
        IC = fma2(ai, c2, IC); RS = fma2(ar, s2, RS);
    }
    float2 rc = unpk(RC), is = unpk(IS), ic = unpk(IC), rs = unpk(RS);
    g_ft[(long)(m * M0 + ky) * (NB * CH) + b * CH + i] =
        make_float2(rc.x + rc.y + is.x + is.y, ic.x + ic.y - rs.x - rs.y);
}

// ---------------- per-mode channel mix ----------------
__global__ void k_mix(int blk) {
    __shared__ float2 F[NB * CH];
    int mode = blockIdx.x;
    const float2* src = g_ft + (long)mode * (NB * CH);
    for (int k = threadIdx.x; k < NB * CH; k += 256) F[k] = src[k];
    __syncthreads();
    const float2* W = g_W + ((long)blk * (NMODE * M0) + mode) * (CH * CH);
    int o = threadIdx.x & 63, bg = threadIdx.x >> 6;
    float accr[4] = {0,0,0,0}, acci[4] = {0,0,0,0};
    for (int i = 0; i < CH; i++) {
        float2 w = W[i * CH + o];
#pragma unroll
        for (int bb = 0; bb < 4; bb++) {
            float2 f = F[(bg * 4 + bb) * CH + i];
            accr[bb] += f.x * w.x - f.y * w.y;
            acci[bb] += f.x * w.y + f.y * w.x;
        }
    }
#pragma unroll
    for (int bb = 0; bb < 4; bb++)
        g_oft[(long)mode * (NB * CH) + (bg * 4 + bb) * CH + o] = make_float2(accr[bb], acci[bb]);
}

// ---------------- inverse x-DFT ----------------
__global__ void k_idftx() {
    __shared__ float2 so[NMODE * M0];
    int b = blockIdx.y, o = blockIdx.x;
    for (int k = threadIdx.x; k < NMODE * M0; k += 256)
        so[k] = g_oft[(long)k * (NB * CH) + b * CH + o];
    __syncthreads();
    int x = threadIdx.x;
    float accr[M0], acci[M0];
#pragma unroll
    for (int ky = 0; ky < M0; ky++) { accr[ky] = 0.f; acci[ky] = 0.f; }
    for (int m = 0; m < NMODE; m++) {
        float c = g_xc[m * 256 + x], s = g_xs[m * 256 + x];
#pragma unroll
        for (int ky = 0; ky < M0; ky++) {
            float2 a = so[m * M0 + ky];
            accr[ky] += a.x * c - a.y * s;
            acci[ky] += a.x * s + a.y * c;
        }
    }
    float2* dst = g_t + ((long)(b * CH + o) * SS + x) * M0;
#pragma unroll
    for (int ky = 0; ky < M0; ky++) dst[ky] = make_float2(accr[ky], acci[ky]);
}

// ---------------- block epilogue (R9 known-good): K=96 GEMM, 256 thr ----------
#define SMEM_FINAL (48*64*8 + 48*66*8 + 64*4)
__global__ void __launch_bounds__(256) k_final(int sel, const float* __restrict__ cw,
                                               const float* __restrict__ cb, int relu) {
    extern __shared__ float sm[];
    u64* wA = (u64*)sm;                    // [48 kp][64 o]
    u64* Bm = wA + 48 * 64;                // [48 kp][66]
    float* cbs = (float*)(Bm + 48 * 66);
    int t = threadIdx.x;
    int b = blockIdx.z, xx = blockIdx.y, yb = blockIdx.x * 64;

    const u64* cwp = (const u64*)cw;
    for (int idx = t; idx < 2048; idx += 256) {
        int o = idx >> 5, ip = idx & 31;
        wA[ip * 64 + o] = cwp[o * 32 + ip];
    }
    for (int idx = t; idx < 512; idx += 256) {
        int o = idx >> 3, kp = idx & 7;
        const float2* tp = g_t + ((long)(b * 64 + o) * 256 + xx) * 16;
        float2 v0 = tp[2 * kp], v1 = tp[2 * kp + 1];
        float f0 = (kp == 0) ? 1.f : 2.f;
        wA[(32 + kp) * 64 + o] = pk(f0 * v0.x, 2.f * v1.x);
        wA[(40 + kp) * 64 + o] = pk(f0 * v0.y, 2.f * v1.y);
    }
    const u64* hp = (const u64*)(g_h2[sel]);
    for (int idx = t; idx < 2048; idx += 256) {
        int ip = idx >> 6, yl = idx & 63;
        Bm[ip * 66 + yl] = hp[((long)(b * 32 + ip) * 256 + xx) * 256 + yb + yl];
    }
    for (int idx = t; idx < 1024; idx += 256) {
        int r = idx >> 6, yl = idx & 63;
        int kp = r & 7, y = yb + yl, ky0 = 2 * kp;
        if (r < 8)
            Bm[(32 + kp) * 66 + yl] = pk(g_tyc[ky0 * 256 + y], g_tyc[(ky0 + 1) * 256 + y]);
        else
            Bm[(40 + kp) * 66 + yl] = pk(g_tys[ky0 * 256 + y], g_tys[(ky0 + 1) * 256 + y]);
    }
    if (t < 64) cbs[t] = cb[t];
    __syncthreads();

    int w = t >> 5, lane = t & 31;
    int ob = w * 8;
    u64 acc[8][2];
#pragma unroll
    for (int oo = 0; oo < 8; oo++) { acc[oo][0] = 0; acc[oo][1] = 0; }

    for (int k = 0; k < 48; k++) {
        u64 b0 = Bm[k * 66 + lane];
        u64 b1 = Bm[k * 66 + 32 + lane];
#pragma unroll
        for (int op = 0; op < 4; op++) {
            u64 a0, a1;
            ldsv2(a0, a1, &wA[k * 64 + ob + 2 * op]);
            acc[2*op  ][0] = fma2(a0, b0, acc[2*op  ][0]);
            acc[2*op  ][1] = fma2(a0, b1, acc[2*op  ][1]);
            acc[2*op+1][0] = fma2(a1, b0, acc[2*op+1][0]);
            acc[2*op+1][1] = fma2(a1, b1, acc[2*op+1][1]);
        }
    }
    __syncthreads();
    u64* S = Bm;
#pragma unroll
    for (int op = 0; op < 4; op++) {
        int o0 = ob + 2 * op;
        float b0f = cbs[o0], b1f = cbs[o0 + 1];
#pragma unroll
        for (int s = 0; s < 2; s++) {
            int y = s * 32 + lane;
            float2 v0 = unpk(acc[2*op][s]), v1 = unpk(acc[2*op+1][s]);
            float r0 = v0.x + v0.y + b0f, r1 = v1.x + v1.y + b1f;
            if (relu) { r0 = fmaxf(r0, 0.f); r1 = fmaxf(r1, 0.f); }
            S[(o0 >> 1) * 66 + y] = pk(r0, r1);
        }
    }
    __syncthreads();
    u64* ho = (u64*)(g_h2[sel ^ 1]);
    for (int idx = t; idx < 2048; idx += 256) {
        int op = idx >> 6, yl = idx & 63;
        ho[((long)(b * 32 + op) * 256 + xx) * 256 + yb + yl] = S[op * 66 + yl];
    }
}

// ---------------- fused fc via mma.sync bf16x3 ----------------
// CTA: 128 pixels x 256 j, K=64; 4 N-passes of 64 j.
// 8 warps = 4 M-groups(32 pix) x 2 N-groups(32 j). smem u32 words, stride 36.
#define AH_OFF 0
#define AL_OFF 4608
#define BH_OFF 9216
#define BL_OFF 11520
#define SRED_OFF 13824
#define B1S_OFF 13952
#define F2S_OFF 14208
#define SMEM_FCM (14464*4)
__global__ void __launch_bounds__(256) k_fc_mma(int sel, const float* __restrict__ fc1b,
                                                const float* __restrict__ fc2w,
                                                const float* __restrict__ fc2b,
                                                float* __restrict__ out) {
    extern __shared__ unsigned smw[];
    unsigned* Ah = smw + AH_OFF;          // [128][36]
    unsigned* Al = smw + AL_OFF;
    unsigned* Bh = smw + BH_OFF;          // [64][36]
    unsigned* Bl = smw + BL_OFF;
    float* sred = (float*)(smw + SRED_OFF);
    float* b1s  = (float*)(smw + B1S_OFF);
    float* f2s  = (float*)(smw + F2S_OFF);
    int t = threadIdx.x;
    int b = blockIdx.z, xx = blockIdx.y, yb = blockIdx.x * 128;

    // A conversion: gmem-coalesced (pix fast), STS 4-way (cheap, once)
    const float2* hp2 = (const float2*)(g_h2[sel]);
    for (int idx = t; idx < 4096; idx += 256) {
        int pix = idx & 127, kp = idx >> 7;
        float2 v = hp2[((long)(b * 32 + kp) * 256 + xx) * 256 + yb + pix];
        __nv_bfloat16 h0 = __float2bfloat16(v.x), h1 = __float2bfloat16(v.y);
        float r0 = v.x - __bfloat162float(h0), r1 = v.y - __bfloat162float(h1);
        __nv_bfloat162 q; q.x = h0; q.y = h1;
        Ah[pix * 36 + kp] = *reinterpret_cast<unsigned*>(&q);
        Al[pix * 36 + kp] = bfpair(r0, r1);
    }
    if (t < 128) sred[t] = 0.f;
    for (int idx = t; idx < 256; idx += 256) { }
    if (t < 256) { b1s[t] = fc1b[t]; f2s[t] = fc2w[t]; }

    int warp = t >> 5, lane = t & 31;
    int mg = warp & 3, ng = warp >> 2;
    int qr = lane >> 2, qc = lane & 3;
    float p[2][2] = {{0.f, 0.f}, {0.f, 0.f}};   // [mt][row-half]

    for (int pass = 0; pass < 4; pass++) {
        int j0 = pass * 64;
        __syncthreads();    // covers A/B before overwrite & first-pass A visibility
        for (int idx = t; idx < 2048; idx += 256) {
            int jr = idx >> 5, kp = idx & 31;
            Bh[jr * 36 + kp] = g_Wh[(j0 + jr) * 32 + kp];
            Bl[jr * 36 + kp] = g_Wl[(j0 + jr) * 32 + kp];
        }
        __syncthreads();

        float acc[2][4][4];
#pragma unroll
        for (int mt = 0; mt < 2; mt++)
#pragma unroll
            for (int nt = 0; nt < 4; nt++)
#pragma unroll
                for (int e = 0; e < 4; e++) acc[mt][nt][e] = 0.f;

#pragma unroll
        for (int kt = 0; kt < 4; kt++) {
            unsigned ah[2][4], al[2][4];
#pragma unroll
            for (int mt = 0; mt < 2; mt++) {
                int r0 = (mg * 32 + mt * 16 + qr) * 36, r1 = r0 + 8 * 36;
                int w0 = kt * 8 + qc;
                ah[mt][0] = Ah[r0 + w0];     ah[mt][1] = Ah[r1 + w0];
                ah[mt][2] = Ah[r0 + w0 + 4]; ah[mt][3] = Ah[r1 + w0 + 4];
                al[mt][0] = Al[r0 + w0];     al[mt][1] = Al[r1 + w0];
                al[mt][2] = Al[r0 + w0 + 4]; al[mt][3] = Al[r1 + w0 + 4];
            }
#pragma unroll
            for (int nt = 0; nt < 4; nt++) {
                int nb = (ng * 32 + nt * 8 + qr) * 36 + kt * 8 + qc;
                unsigned bh0 = Bh[nb], bh1 = Bh[nb + 4];
                unsigned bl0 = Bl[nb], bl1 = Bl[nb + 4];
#pragma unroll
                for (int mt = 0; mt < 2; mt++) {
                    mma_bf16(acc[mt][nt], ah[mt], bh0, bh1);
                    mma_bf16(acc[mt][nt], al[mt], bh0, bh1);
                    mma_bf16(acc[mt][nt], ah[mt], bl0, bl1);
                }
            }
        }
        // fold this pass into per-pixel partials
#pragma unroll
        for (int mt = 0; mt < 2; mt++)
#pragma unroll
            for (int nt = 0; nt < 4; nt++) {
                int jc = j0 + ng * 32 + nt * 8 + qc * 2;
                float bb0 = b1s[jc], ff0 = f2s[jc];
                float bb1 = b1s[jc + 1], ff1 = f2s[jc + 1];
                p[mt][0] += fmaxf(acc[mt][nt][0] + bb0, 0.f) * ff0
                          + fmaxf(acc[mt][nt][1] + bb1, 0.f) * ff1;
                p[mt][1] += fmaxf(acc[mt][nt][2] + bb0, 0.f) * ff0
                          + fmaxf(acc[mt][nt][3] + bb1, 0.f) * ff1;
            }
    }
#pragma unroll
    for (int mt = 0; mt < 2; mt++) {
        atomicAdd(&sred[mg * 32 + mt * 16 + qr], p[mt][0]);
        atomicAdd(&sred[mg * 32 + mt * 16 + 8 + qr], p[mt][1]);
    }
    __syncthreads();
    if (t < 128) out[((long)b * 256 + xx) * 256 + yb + t] = sred[t] + fc2b[0];
}

// ---------------- launch ----------------
extern "C" void kernel_launch(void* const* d_in, const int* in_sizes, int n_in,
                              void* d_out, int out_size) {
    const float* x    = (const float*)d_in[0];
    const float* fc0w = (const float*)d_in[1];
    const float* fc0b = (const float*)d_in[2];
    const float2* w1  = (const float2*)d_in[3];
    const float2* w2  = (const float2*)d_in[4];
    const float* cw   = (const float*)d_in[5];
    const float* cb   = (const float*)d_in[6];
    const float* fc1w = (const float*)d_in[7];
    const float* fc1b = (const float*)d_in[8];
    const float* fc2w = (const float*)d_in[9];
    const float* fc2b = (const float*)d_in[10];
    float* out = (float*)d_out;

    cudaFuncSetAttribute(k_dfty,   cudaFuncAttributeMaxDynamicSharedMemorySize, SMEM_DFTY);
    cudaFuncSetAttribute(k_final,  cudaFuncAttributeMaxDynamicSharedMemorySize, SMEM_FINAL);
    cudaFuncSetAttribute(k_fc_mma, cudaFuncAttributeMaxDynamicSharedMemorySize, SMEM_FCM);

    k_trig<<<48, 256>>>();
    k_wprep<<<(4 * NMODE * M0 * CH * CH) / 256, 256>>>(w1, w2);
    k_fcprep<<<32, 256>>>(fc1w);
    k_lift<<<dim3(SS, NB), 256>>>(x, fc0w, fc0b);

    int cur = 0;
    for (int blk = 0; blk < 4; blk++) {
        k_dfty<<<dim3(32, 4, NB), 128, SMEM_DFTY>>>(cur);
        k_dftx<<<dim3(CH, NB), 512>>>();
        k_mix<<<NMODE * M0, 256>>>(blk);
        k_idftx<<<dim3(CH, NB), 256>>>();
        k_final<<<dim3(4, SS, NB), 256, SMEM_FINAL>>>(cur, cw + (long)blk * CH * CH,
                                                      cb + blk * CH, blk < 3 ? 1 : 0);
        cur ^= 1;
    }
    k_fc_mma<<<dim3(2, SS, NB), 256, SMEM_FCM>>>(cur, fc1b, fc2w, fc2b, out);
}

// round 16
// speedup vs baseline: 2.1125x; 1.1240x over previous
#include <cuda_runtime.h>
#include <cuda_bf16.h>

#define NB 16
#define CH 64
#define SS 256
#define M0 16
#define NMODE 32
#define PLANE (SS*SS)

typedef unsigned long long u64;

__device__ __forceinline__ u64 fma2(u64 a, u64 b, u64 c) {
    u64 d; asm("fma.rn.f32x2 %0,%1,%2,%3;" : "=l"(d) : "l"(a), "l"(b), "l"(c)); return d;
}
__device__ __forceinline__ float2 unpk(u64 v) {
    unsigned lo, hi; asm("mov.b64 {%0,%1},%2;" : "=r"(lo), "=r"(hi) : "l"(v));
    return make_float2(__uint_as_float(lo), __uint_as_float(hi));
}
__device__ __forceinline__ u64 pk(float a, float b) {
    u64 d; asm("mov.b64 %0,{%1,%2};" : "=l"(d) : "r"(__float_as_uint(a)), "r"(__float_as_uint(b)));
    return d;
}
__device__ __forceinline__ void ldsv2(u64& a, u64& b, const void* p) {
    unsigned ad = (unsigned)__cvta_generic_to_shared(p);
    asm("ld.shared.v2.u64 {%0,%1},[%2];" : "=l"(a), "=l"(b) : "r"(ad));
}
__device__ __forceinline__ unsigned bfpair(float lo, float hi) {
    __nv_bfloat162 q;
    q.x = __float2bfloat16(lo); q.y = __float2bfloat16(hi);
    return *reinterpret_cast<unsigned*>(&q);
}
__device__ __forceinline__ void mma_bf16(float* c, const unsigned* a, unsigned b0, unsigned b1) {
    asm("mma.sync.aligned.m16n8k16.row.col.f32.bf16.bf16.f32 "
        "{%0,%1,%2,%3}, {%4,%5,%6,%7}, {%8,%9}, {%0,%1,%2,%3};"
        : "+f"(c[0]), "+f"(c[1]), "+f"(c[2]), "+f"(c[3])
        : "r"(a[0]), "r"(a[1]), "r"(a[2]), "r"(a[3]), "r"(b0), "r"(b1));
}

// ---------------- device scratch ----------------
__device__ float  g_h2[2][NB*32*SS*SS*2];      // [b][c/2][x][y][2]
__device__ float  g_Ar[NB*CH*M0*SS];           // [b][c][ky][x]
__device__ float  g_Ai[NB*CH*M0*SS];
__device__ float2 g_ft[NMODE*M0*NB*CH];        // [mode][b][i]
__device__ float2 g_oft[NMODE*M0*NB*CH];
__device__ float2 g_t [NB*CH*SS*M0];           // [b][o][x][ky]
__device__ float2 g_W [4*NMODE*M0*CH*CH];      // [blk][mode][i][o]
__device__ float  g_tyc[M0*SS];                // cos(2pi ky y/256)
__device__ float  g_tys[M0*SS];                // -sin
__device__ float  g_xc[NMODE*SS];              // cos(2pi kxp x/256)
__device__ float  g_xs[NMODE*SS];              // sin
__device__ float4 g_ty4[M0*SS];                // (c,c,-s,-s)
__device__ unsigned g_Wh[256*32];              // fc1w bf16-hi pairs [j][kp]
__device__ unsigned g_Wl[256*32];
__device__ unsigned g_CWh[4*64*32];            // cw bf16-hi pairs [blk][o][ip]
__device__ unsigned g_CWl[4*64*32];
__device__ unsigned g_TRh[256*16];             // trig pairs [y][q] (cos q<8, -sin q>=8)
__device__ unsigned g_TRl[256*16];

// ---------------- trig tables ----------------
__global__ void k_trig() {
    int t = blockIdx.x * blockDim.x + threadIdx.x;
    if (t < M0 * SS) {
        int ky = t >> 8, y = t & 255;
        float s, c;
        sincospif((float)(ky * y) / 128.0f, &s, &c);   // exact integer arg
        g_tyc[t] = c; g_tys[t] = -s;
        g_ty4[t] = make_float4(c, c, -s, -s);
    } else if (t < M0 * SS + NMODE * SS) {
        int k = t - M0 * SS;
        int m = k >> 8, x = k & 255;
        int kxp = (m < 16) ? m : (m - 32);
        float s, c;
        sincospif((float)(kxp * x) / 128.0f, &s, &c);
        g_xc[k] = c; g_xs[k] = s;
    } else if (t < M0 * SS + NMODE * SS + 256 * 16) {
        int k = t - M0 * SS - NMODE * SS;
        int y = k >> 4, q = k & 15;
        int ky0 = (q & 7) * 2;
        float s0, c0, s1, c1;
        sincospif((float)(ky0 * y) / 128.0f, &s0, &c0);
        sincospif((float)((ky0 + 1) * y) / 128.0f, &s1, &c1);
        float v0 = (q < 8) ? c0 : -s0;
        float v1 = (q < 8) ? c1 : -s1;
        __nv_bfloat16 h0 = __float2bfloat16(v0), h1 = __float2bfloat16(v1);
        __nv_bfloat162 qq; qq.x = h0; qq.y = h1;
        g_TRh[k] = *reinterpret_cast<unsigned*>(&qq);
        g_TRl[k] = bfpair(v0 - __bfloat162float(h0), v1 - __bfloat162float(h1));
    }
}

// ---------------- weight re-layouts ----------------
__global__ void k_wprep(const float2* __restrict__ w1, const float2* __restrict__ w2) {
    int idx = blockIdx.x * blockDim.x + threadIdx.x;
    int o = idx & 63, i = (idx >> 6) & 63, ky = (idx >> 12) & 15;
    int m = (idx >> 16) & 31, blk = (idx >> 21);
    const float2* src = (m < 16) ? w1 : w2;
    int mx = (m < 16) ? m : (m - 16);
    g_W[idx] = src[((((long)blk * 64 + i) * 64 + o) * 16 + mx) * 16 + ky];
}

__global__ void k_fcprep(const float* __restrict__ fc1w) {
    int idx = blockIdx.x * 256 + threadIdx.x;   // 8192: j*32+kp
    int j = idx >> 5, kp = idx & 31;
    float w0 = fc1w[(2 * kp) * 256 + j], w1 = fc1w[(2 * kp + 1) * 256 + j];
    __nv_bfloat16 h0 = __float2bfloat16(w0), h1 = __float2bfloat16(w1);
    float r0 = w0 - __bfloat162float(h0), r1 = w1 - __bfloat162float(h1);
    __nv_bfloat162 q; q.x = h0; q.y = h1;
    g_Wh[idx] = *reinterpret_cast<unsigned*>(&q);
    g_Wl[idx] = bfpair(r0, r1);
}

__global__ void k_cwprep(const float* __restrict__ cw) {
    int idx = blockIdx.x * 256 + threadIdx.x;   // 8192: blk*2048 + o*32 + ip
    int ip = idx & 31, o = (idx >> 5) & 63, blk = idx >> 11;
    long base = ((long)blk * 64 + o) * 64;
    float w0 = cw[base + 2 * ip], w1 = cw[base + 2 * ip + 1];
    __nv_bfloat16 h0 = __float2bfloat16(w0), h1 = __float2bfloat16(w1);
    __nv_bfloat162 q; q.x = h0; q.y = h1;
    g_CWh[idx] = *reinterpret_cast<unsigned*>(&q);
    g_CWl[idx] = bfpair(w0 - __bfloat162float(h0), w1 - __bfloat162float(h1));
}

// ---------------- lift ----------------
__global__ void k_lift(const float* __restrict__ x, const float* __restrict__ w0,
                       const float* __restrict__ b0) {
    __shared__ float sw[192], sb[64];
    int t = threadIdx.x;
    if (t < 192) sw[t] = w0[t];
    if (t < 64)  sb[t] = b0[t];
    __syncthreads();
    int b = blockIdx.y, xx = blockIdx.x, y = t;
    const float* xp = x + (((long)b * SS + xx) * SS + y) * 3;
    float x0 = xp[0], x1 = xp[1], x2 = xp[2];
    float2* out = (float2*)g_h2[0];
#pragma unroll
    for (int cp = 0; cp < 32; cp++) {
        int c0 = 2 * cp;
        float v0 = x0 * sw[c0]   + x1 * sw[64 + c0]   + x2 * sw[128 + c0]   + sb[c0];
        float v1 = x0 * sw[c0+1] + x1 * sw[64 + c0+1] + x2 * sw[128 + c0+1] + sb[c0+1];
        out[((long)(b * 32 + cp) * SS + xx) * SS + y] = make_float2(v0, v1);
    }
}

// ---------------- forward y-DFT (R9 known-good) ----------------
#define SMEM_DFTY (32*65*8 + 16*32*16)
__global__ void __launch_bounds__(128) k_dfty(int sel) {
    extern __shared__ float sm[];
    u64* sh = (u64*)sm;                          // [32 y][65 x]
    float4* t4 = (float4*)(sm + 32 * 65 * 2);    // [16 ky][32 y]
    int b = blockIdx.z, xq = blockIdx.y, cp = blockIdx.x, t = threadIdx.x;
    const u64* gp = (const u64*)(g_h2[sel]) + (long)(b * 32 + cp) * PLANE
                  + (long)(xq * 64) * SS;
    int w = t >> 5, lane = t & 31, ky0 = w * 4;
    u64 aR[2][4], aI[2][4];
#pragma unroll
    for (int j = 0; j < 2; j++)
#pragma unroll
        for (int k = 0; k < 4; k++) { aR[j][k] = 0; aI[j][k] = 0; }

    for (int yc = 0; yc < 8; yc++) {
#pragma unroll
        for (int i = 0; i < 16; i++) {
            int idx = i * 128 + t, xx = idx >> 5, yy = idx & 31;
            sh[yy * 65 + xx] = gp[xx * 256 + yc * 32 + yy];
        }
#pragma unroll
        for (int i = 0; i < 4; i++) {
            int idx = i * 128 + t, ky = idx >> 5, yy = idx & 31;
            t4[idx] = g_ty4[ky * 256 + yc * 32 + yy];
        }
        __syncthreads();
#pragma unroll 8
        for (int y = 0; y < 32; y++) {
            u64 h1 = sh[y * 65 + lane], h2v = sh[y * 65 + 32 + lane];
#pragma unroll
            for (int k = 0; k < 4; k++) {
                u64 cc, ss;
                ldsv2(cc, ss, &t4[(ky0 + k) * 32 + y]);
                aR[0][k] = fma2(h1, cc, aR[0][k]);  aI[0][k] = fma2(h1, ss, aI[0][k]);
                aR[1][k] = fma2(h2v, cc, aR[1][k]); aI[1][k] = fma2(h2v, ss, aI[1][k]);
            }
        }
        __syncthreads();
    }
    const float sc = 1.0f / 65536.0f;
#pragma unroll
    for (int j = 0; j < 2; j++) {
        int x = xq * 64 + lane + j * 32;
#pragma unroll
        for (int k = 0; k < 4; k++) {
            int ky = ky0 + k;
            long p0 = ((long)((b * 64 + 2 * cp) * 16 + ky)) * 256 + x;
            long p1 = ((long)((b * 64 + 2 * cp + 1) * 16 + ky)) * 256 + x;
            float2 r = unpk(aR[j][k]), ii = unpk(aI[j][k]);
            g_Ar[p0] = r.x * sc;  g_Ar[p1] = r.y * sc;
            g_Ai[p0] = ii.x * sc; g_Ai[p1] = ii.y * sc;
        }
    }
}

// ---------------- forward x-DFT ----------------
__global__ void __launch_bounds__(512) k_dftx() {
    __shared__ float sAr[16 * 258];
    __shared__ float sAi[16 * 258];
    int b = blockIdx.y, i = blockIdx.x;
    long abase = (long)((b * CH + i) * M0) * SS;
    for (int k = threadIdx.x; k < 4096; k += 512) {
        int ky = k >> 8, x = k & 255;
        sAr[ky * 258 + x] = g_Ar[abase + k];
        sAi[ky * 258 + x] = g_Ai[abase + k];
    }
    __syncthreads();
    int ky = threadIdx.x & 15, m = threadIdx.x >> 4;
    const u64* arp = (const u64*)(sAr + ky * 258);
    const u64* aip = (const u64*)(sAi + ky * 258);
    const u64* cp = (const u64*)(g_xc + m * 256);
    const u64* sp = (const u64*)(g_xs + m * 256);
    u64 RC = 0, IS = 0, IC = 0, RS = 0;
#pragma unroll 8
    for (int xp = 0; xp < 128; xp++) {
        u64 c2 = cp[xp], s2 = sp[xp];
        u64 ar = arp[xp], ai = aip[xp];
        RC = fma2(ar, c2, RC); IS = fma2(ai, s2, IS);
        IC = fma2(ai, c2, IC); RS = fma2(ar, s2, RS);
    }
    float2 rc = unpk(RC), is = unpk(IS), ic = unpk(IC), rs = unpk(RS);
    g_ft[(long)(m * M0 + ky) * (NB * CH) + b * CH + i] =
        make_float2(rc.x + rc.y + is.x + is.y, ic.x + ic.y - rs.x - rs.y);
}

// ---------------- per-mode channel mix ----------------
__global__ void k_mix(int blk) {
    __shared__ float2 F[NB * CH];
    int mode = blockIdx.x;
    const float2* src = g_ft + (long)mode * (NB * CH);
    for (int k = threadIdx.x; k < NB * CH; k += 256) F[k] = src[k];
    __syncthreads();
    const float2* W = g_W + ((long)blk * (NMODE * M0) + mode) * (CH * CH);
    int o = threadIdx.x & 63, bg = threadIdx.x >> 6;
    float accr[4] = {0,0,0,0}, acci[4] = {0,0,0,0};
    for (int i = 0; i < CH; i++) {
        float2 w = W[i * CH + o];
#pragma unroll
        for (int bb = 0; bb < 4; bb++) {
            float2 f = F[(bg * 4 + bb) * CH + i];
            accr[bb] += f.x * w.x - f.y * w.y;
            acci[bb] += f.x * w.y + f.y * w.x;
        }
    }
#pragma unroll
    for (int bb = 0; bb < 4; bb++)
        g_oft[(long)mode * (NB * CH) + (bg * 4 + bb) * CH + o] = make_float2(accr[bb], acci[bb]);
}

// ---------------- inverse x-DFT ----------------
__global__ void k_idftx() {
    __shared__ float2 so[NMODE * M0];
    int b = blockIdx.y, o = blockIdx.x;
    for (int k = threadIdx.x; k < NMODE * M0; k += 256)
        so[k] = g_oft[(long)k * (NB * CH) + b * CH + o];
    __syncthreads();
    int x = threadIdx.x;
    float accr[M0], acci[M0];
#pragma unroll
    for (int ky = 0; ky < M0; ky++) { accr[ky] = 0.f; acci[ky] = 0.f; }
    for (int m = 0; m < NMODE; m++) {
        float c = g_xc[m * 256 + x], s = g_xs[m * 256 + x];
#pragma unroll
        for (int ky = 0; ky < M0; ky++) {
            float2 a = so[m * M0 + ky];
            accr[ky] += a.x * c - a.y * s;
            acci[ky] += a.x * s + a.y * c;
        }
    }
    float2* dst = g_t + ((long)(b * CH + o) * SS + x) * M0;
#pragma unroll
    for (int ky = 0; ky < M0; ky++) dst[ky] = make_float2(accr[ky], acci[ky]);
}

// ---------------- block epilogue via mma.sync bf16x3 ----------------
// D[64 o][64 y] = A[96 k][64 o]^T B[96 k][64 y]; K rows: 0-63 conv, 64-79 tx*cos,
// 80-95 ty*(-sin). A row-major [o][kp], B col-form [y][kp], stride 52 words.
#define FM_STR 52
#define FM_AH 0
#define FM_AL 3328
#define FM_BH 6656
#define FM_BL 9984
#define FM_CBS 13312
#define SMEM_FINALM (13376*4)
__global__ void __launch_bounds__(256) k_final_mma(int sel, int blk,
                                                   const float* __restrict__ cb, int relu) {
    extern __shared__ unsigned smw[];
    unsigned* Ah = smw + FM_AH;           // [64 o][52]
    unsigned* Al = smw + FM_AL;
    unsigned* Bh = smw + FM_BH;           // [64 y][52]
    unsigned* Bl = smw + FM_BL;
    float* cbs = (float*)(smw + FM_CBS);
    int t = threadIdx.x;
    int b = blockIdx.z, xx = blockIdx.y, yb = blockIdx.x * 64;

    // A conv rows (pre-split weights)
    for (int idx = t; idx < 2048; idx += 256) {
        int o = idx >> 5, ip = idx & 31;
        Ah[o * FM_STR + ip] = g_CWh[blk * 2048 + idx];
        Al[o * FM_STR + ip] = g_CWl[blk * 2048 + idx];
    }
    // A spectral rows: f*t.x / f*t.y
    for (int idx = t; idx < 1024; idx += 256) {
        int o = idx >> 4, q = idx & 15;
        const float2* tp = g_t + ((long)(b * 64 + o) * 256 + xx) * 16;
        int ky0 = (q & 7) * 2;
        float2 ta = tp[ky0], tb = tp[ky0 + 1];
        float f0 = (ky0 == 0) ? 1.f : 2.f;
        float v0 = (q < 8) ? f0 * ta.x : f0 * ta.y;
        float v1 = (q < 8) ? 2.f * tb.x : 2.f * tb.y;
        __nv_bfloat16 h0 = __float2bfloat16(v0), h1 = __float2bfloat16(v1);
        __nv_bfloat162 qq; qq.x = h0; qq.y = h1;
        Ah[o * FM_STR + 32 + q] = *reinterpret_cast<unsigned*>(&qq);
        Al[o * FM_STR + 32 + q] = bfpair(v0 - __bfloat162float(h0), v1 - __bfloat162float(h1));
    }
    // B h rows (channel pairs)
    const float2* hp2 = (const float2*)(g_h2[sel]);
    for (int idx = t; idx < 2048; idx += 256) {
        int yl = idx & 63, kp = idx >> 6;
        float2 v = hp2[((long)(b * 32 + kp) * 256 + xx) * 256 + yb + yl];
        __nv_bfloat16 h0 = __float2bfloat16(v.x), h1 = __float2bfloat16(v.y);
        __nv_bfloat162 qq; qq.x = h0; qq.y = h1;
        Bh[yl * FM_STR + kp] = *reinterpret_cast<unsigned*>(&qq);
        Bl[yl * FM_STR + kp] = bfpair(v.x - __bfloat162float(h0), v.y - __bfloat162float(h1));
    }
    // B trig rows (pre-split tables)
    for (int idx = t; idx < 1024; idx += 256) {
        int yl = idx & 63, q = idx >> 6;
        Bh[yl * FM_STR + 32 + q] = g_TRh[(yb + yl) * 16 + q];
        Bl[yl * FM_STR + 32 + q] = g_TRl[(yb + yl) * 16 + q];
    }
    if (t < 64) cbs[t] = cb[t];
    __syncthreads();

    int warp = t >> 5, lane = t & 31;
    int mg = warp & 3, ng = warp >> 2;     // o-base mg*16, y-base ng*32
    int qr = lane >> 2, qc = lane & 3;
    float acc[4][4];
#pragma unroll
    for (int nt = 0; nt < 4; nt++)
#pragma unroll
        for (int e = 0; e < 4; e++) acc[nt][e] = 0.f;

#pragma unroll
    for (int kt = 0; kt < 6; kt++) {
        unsigned ah[4], al[4];
        int r0 = (mg * 16 + qr) * FM_STR, r1 = r0 + 8 * FM_STR, w0 = kt * 8 + qc;
        ah[0] = Ah[r0 + w0]; ah[1] = Ah[r1 + w0];
        ah[2] = Ah[r0 + w0 + 4]; ah[3] = Ah[r1 + w0 + 4];
        al[0] = Al[r0 + w0]; al[1] = Al[r1 + w0];
        al[2] = Al[r0 + w0 + 4]; al[3] = Al[r1 + w0 + 4];
#pragma unroll
        for (int nt = 0; nt < 4; nt++) {
            int nb = (ng * 32 + nt * 8 + qr) * FM_STR + kt * 8 + qc;
            unsigned bh0 = Bh[nb], bh1 = Bh[nb + 4];
            unsigned bl0 = Bl[nb], bl1 = Bl[nb + 4];
            mma_bf16(acc[nt], ah, bh0, bh1);
            mma_bf16(acc[nt], al, bh0, bh1);
            mma_bf16(acc[nt], ah, bl0, bl1);
        }
    }
    __syncthreads();                      // done reading A/B; reuse as stage S
    float* S = (float*)smw;               // [64 o][66 y]
#pragma unroll
    for (int nt = 0; nt < 4; nt++) {
        int o0 = mg * 16 + qr;
        int y0 = ng * 32 + nt * 8 + qc * 2;
        float bias0 = cbs[o0], bias8 = cbs[o0 + 8];
        float r;
        r = acc[nt][0] + bias0; if (relu) r = fmaxf(r, 0.f); S[o0 * 66 + y0] = r;
        r = acc[nt][1] + bias0; if (relu) r = fmaxf(r, 0.f); S[o0 * 66 + y0 + 1] = r;
        r = acc[nt][2] + bias8; if (relu) r = fmaxf(r, 0.f); S[(o0 + 8) * 66 + y0] = r;
        r = acc[nt][3] + bias8; if (relu) r = fmaxf(r, 0.f); S[(o0 + 8) * 66 + y0 + 1] = r;
    }
    __syncthreads();
    u64* ho = (u64*)(g_h2[sel ^ 1]);
    for (int idx = t; idx < 2048; idx += 256) {
        int yl = idx & 63, op = idx >> 6;
        ho[((long)(b * 32 + op) * 256 + xx) * 256 + yb + yl] =
            pk(S[(2 * op) * 66 + yl], S[(2 * op + 1) * 66 + yl]);
    }
}

// ---------------- fused fc via mma.sync bf16x3 (R14 known-good) ----------------
#define AH_OFF 0
#define AL_OFF 4608
#define BH_OFF 9216
#define BL_OFF 11520
#define SRED_OFF 13824
#define B1S_OFF 13952
#define F2S_OFF 14208
#define SMEM_FCM (14464*4)
__global__ void __launch_bounds__(256) k_fc_mma(int sel, const float* __restrict__ fc1b,
                                                const float* __restrict__ fc2w,
                                                const float* __restrict__ fc2b,
                                                float* __restrict__ out) {
    extern __shared__ unsigned smw[];
    unsigned* Ah = smw + AH_OFF;          // [128][36]
    unsigned* Al = smw + AL_OFF;
    unsigned* Bh = smw + BH_OFF;          // [64][36]
    unsigned* Bl = smw + BL_OFF;
    float* sred = (float*)(smw + SRED_OFF);
    float* b1s  = (float*)(smw + B1S_OFF);
    float* f2s  = (float*)(smw + F2S_OFF);
    int t = threadIdx.x;
    int b = blockIdx.z, xx = blockIdx.y, yb = blockIdx.x * 128;

    const float2* hp2 = (const float2*)(g_h2[sel]);
    for (int idx = t; idx < 4096; idx += 256) {
        int pix = idx & 127, kp = idx >> 7;
        float2 v = hp2[((long)(b * 32 + kp) * 256 + xx) * 256 + yb + pix];
        __nv_bfloat16 h0 = __float2bfloat16(v.x), h1 = __float2bfloat16(v.y);
        float r0 = v.x - __bfloat162float(h0), r1 = v.y - __bfloat162float(h1);
        __nv_bfloat162 q; q.x = h0; q.y = h1;
        Ah[pix * 36 + kp] = *reinterpret_cast<unsigned*>(&q);
        Al[pix * 36 + kp] = bfpair(r0, r1);
    }
    if (t < 128) sred[t] = 0.f;
    if (t < 256) { b1s[t] = fc1b[t]; f2s[t] = fc2w[t]; }

    int warp = t >> 5, lane = t & 31;
    int mg = warp & 3, ng = warp >> 2;
    int qr = lane >> 2, qc = lane & 3;
    float p[2][2] = {{0.f, 0.f}, {0.f, 0.f}};

    for (int pass = 0; pass < 4; pass++) {
        int j0 = pass * 64;
        __syncthreads();
        for (int idx = t; idx < 2048; idx += 256) {
            int jr = idx >> 5, kp = idx & 31;
            Bh[jr * 36 + kp] = g_Wh[(j0 + jr) * 32 + kp];
            Bl[jr * 36 + kp] = g_Wl[(j0 + jr) * 32 + kp];
        }
        __syncthreads();

        float acc[2][4][4];
#pragma unroll
        for (int mt = 0; mt < 2; mt++)
#pragma unroll
            for (int nt = 0; nt < 4; nt++)
#pragma unroll
                for (int e = 0; e < 4; e++) acc[mt][nt][e] = 0.f;

#pragma unroll
        for (int kt = 0; kt < 4; kt++) {
            unsigned ah[2][4], al[2][4];
#pragma unroll
            for (int mt = 0; mt < 2; mt++) {
                int r0 = (mg * 32 + mt * 16 + qr) * 36, r1 = r0 + 8 * 36;
                int w0 = kt * 8 + qc;
                ah[mt][0] = Ah[r0 + w0];     ah[mt][1] = Ah[r1 + w0];
                ah[mt][2] = Ah[r0 + w0 + 4]; ah[mt][3] = Ah[r1 + w0 + 4];
                al[mt][0] = Al[r0 + w0];     al[mt][1] = Al[r1 + w0];
                al[mt][2] = Al[r0 + w0 + 4]; al[mt][3] = Al[r1 + w0 + 4];
            }
#pragma unroll
            for (int nt = 0; nt < 4; nt++) {
                int nb = (ng * 32 + nt * 8 + qr) * 36 + kt * 8 + qc;
                unsigned bh0 = Bh[nb], bh1 = Bh[nb + 4];
                unsigned bl0 = Bl[nb], bl1 = Bl[nb + 4];
#pragma unroll
                for (int mt = 0; mt < 2; mt++) {
                    mma_bf16(acc[mt][nt], ah[mt], bh0, bh1);
                    mma_bf16(acc[mt][nt], al[mt], bh0, bh1);
                    mma_bf16(acc[mt][nt], ah[mt], bl0, bl1);
                }
            }
        }
#pragma unroll
        for (int mt = 0; mt < 2; mt++)
#pragma unroll
            for (int nt = 0; nt < 4; nt++) {
                int jc = j0 + ng * 32 + nt * 8 + qc * 2;
                float bb0 = b1s[jc], ff0 = f2s[jc];
                float bb1 = b1s[jc + 1], ff1 = f2s[jc + 1];
                p[mt][0] += fmaxf(acc[mt][nt][0] + bb0, 0.f) * ff0
                          + fmaxf(acc[mt][nt][1] + bb1, 0.f) * ff1;
                p[mt][1] += fmaxf(acc[mt][nt][2] + bb0, 0.f) * ff0
                          + fmaxf(acc[mt][nt][3] + bb1, 0.f) * ff1;
            }
    }
#pragma unroll
    for (int mt = 0; mt < 2; mt++) {
        atomicAdd(&sred[mg * 32 + mt * 16 + qr], p[mt][0]);
        atomicAdd(&sred[mg * 32 + mt * 16 + 8 + qr], p[mt][1]);
    }
    __syncthreads();
    if (t < 128) out[((long)b * 256 + xx) * 256 + yb + t] = sred[t] + fc2b[0];
}

// ---------------- launch ----------------
extern "C" void kernel_launch(void* const* d_in, const int* in_sizes, int n_in,
                              void* d_out, int out_size) {
    const float* x    = (const float*)d_in[0];
    const float* fc0w = (const float*)d_in[1];
    const float* fc0b = (const float*)d_in[2];
    const float2* w1  = (const float2*)d_in[3];
    const float2* w2  = (const float2*)d_in[4];
    const float* cw   = (const float*)d_in[5];
    const float* cb   = (const float*)d_in[6];
    const float* fc1w = (const float*)d_in[7];
    const float* fc1b = (const float*)d_in[8];
    const float* fc2w = (const float*)d_in[9];
    const float* fc2b = (const float*)d_in[10];
    float* out = (float*)d_out;

    cudaFuncSetAttribute(k_dfty,      cudaFuncAttributeMaxDynamicSharedMemorySize, SMEM_DFTY);
    cudaFuncSetAttribute(k_final_mma, cudaFuncAttributeMaxDynamicSharedMemorySize, SMEM_FINALM);
    cudaFuncSetAttribute(k_fc_mma,    cudaFuncAttributeMaxDynamicSharedMemorySize, SMEM_FCM);

    k_trig<<<64, 256>>>();
    k_wprep<<<(4 * NMODE * M0 * CH * CH) / 256, 256>>>(w1, w2);
    k_fcprep<<<32, 256>>>(fc1w);
    k_cwprep<<<32, 256>>>(cw);
    k_lift<<<dim3(SS, NB), 256>>>(x, fc0w, fc0b);

    int cur = 0;
    for (int blk = 0; blk < 4; blk++) {
        k_dfty<<<dim3(32, 4, NB), 128, SMEM_DFTY>>>(cur);
        k_dftx<<<dim3(CH, NB), 512>>>();
        k_mix<<<NMODE * M0, 256>>>(blk);
        k_idftx<<<dim3(CH, NB), 256>>>();
        k_final_mma<<<dim3(4, SS, NB), 256, SMEM_FINALM>>>(cur, blk, cb + blk * CH,
                                                           blk < 3 ? 1 : 0);
        cur ^= 1;
    }
    k_fc_mma<<<dim3(2, SS, NB), 256, SMEM_FCM>>>(cur, fc1b, fc2w, fc2b, out);
}